// round 5
// baseline (speedup 1.0000x reference)
#include <cuda_runtime.h>

#define NPLANES 32
#define HW 65536

// Ping-pong scratch (allocation-free: __device__ globals)
static __device__ float g_bufA[NPLANES * HW];
static __device__ float g_bufB[NPLANES * HW];

// ---------------------------------------------------------------------------
// Horizontal pass: weighted sliding max/min along x.
//   out[p] = max_j in[p+j] - c*se(j)   (ISMAX)   or   min_j in[p+j] + c*se(j)
//   se(j) = j^2 * 2^-TL  (exact dyadic), TL = log2(4*t_k)
// Block: 256 threads = 8 rows x 32 lanes; each thread -> 8 consecutive x.
// ---------------------------------------------------------------------------
template <int W, int TL, bool ISMAX>
__global__ __launch_bounds__(256) void hpass(const float* __restrict__ src,
                                             float* __restrict__ dst,
                                             const float* __restrict__ coefp)
{
    constexpr float SESC = 1.0f / (float)(1 << TL);
    constexpr int RW = 256 + 2 * W;
    const float c = ISMAX ? -__ldg(coefp) : __ldg(coefp);
    const float PAD = ISMAX ? -10000.0f : 10000.0f;

    __shared__ float s[8][RW];
    const int plane = blockIdx.y;
    const int rowbase = blockIdx.x * 8;
    const float* sp = src + plane * HW + rowbase * 256;
    const int t = threadIdx.x;

    // Stage 8 padded rows into smem
    for (int idx = t; idx < 8 * RW; idx += 256) {
        int rr = idx / RW;
        int pp = idx - rr * RW;
        int xx = pp - W;
        s[rr][pp] = ((unsigned)xx < 256u) ? sp[rr * 256 + xx] : PAD;
    }
    __syncthreads();

    const int r  = t >> 5;
    const int x0 = (t & 31) * 8;

    float acc[8];
#pragma unroll
    for (int i = 0; i < 8; i++) acc[i] = ISMAX ? -3.0e38f : 3.0e38f;

    // Source-centric sweep: each smem value read once, feeds up to 8 outputs.
#pragma unroll
    for (int u = 0; u < 2 * W + 8; ++u) {
        const float v = s[r][x0 + u];
#pragma unroll
        for (int i = 0; i < 8; ++i) {
            const int j = u - W - i;            // tap offset for output i
            if (j >= -W && j <= W) {
                const float se = (float)(j * j) * SESC;   // compile-time const
                const float cand = fmaf(c, se, v);        // v -/+ coef*se
                acc[i] = ISMAX ? fmaxf(acc[i], cand) : fminf(acc[i], cand);
            }
        }
    }

    float* dp = dst + plane * HW + (rowbase + r) * 256 + x0;
#pragma unroll
    for (int i = 0; i < 8; i++) dp[i] = acc[i];
}

// ---------------------------------------------------------------------------
// Vertical pass: weighted sliding max/min along y, float2-vectorized in x.
// Block: 256 threads = 2 y-subgroups x 128 x-pairs; thread -> 8 rows x 2 cols.
// dstPlaneStride: HW for intermediates, 4*HW when writing the stacked output.
// ---------------------------------------------------------------------------
template <int W, int TL, bool ISMAX>
__global__ __launch_bounds__(256) void vpass(const float* __restrict__ src,
                                             float* __restrict__ dst,
                                             const float* __restrict__ coefp,
                                             int dstPlaneStride)
{
    constexpr float SESC = 1.0f / (float)(1 << TL);
    const float c = ISMAX ? -__ldg(coefp) : __ldg(coefp);
    const float PAD = ISMAX ? -10000.0f : 10000.0f;

    const int plane = blockIdx.y;
    const int t = threadIdx.x;
    const int x  = (t & 127) * 2;
    const int y0 = blockIdx.x * 16 + (t >> 7) * 8;
    const float* sp = src + plane * HW + x;

    float2 acc[8];
    const float INITV = ISMAX ? -3.0e38f : 3.0e38f;
#pragma unroll
    for (int i = 0; i < 8; i++) { acc[i].x = INITV; acc[i].y = INITV; }

#pragma unroll
    for (int u = 0; u < 2 * W + 8; ++u) {
        const int y = y0 - W + u;
        float2 v;
        if ((unsigned)y < 256u) v = *(const float2*)(sp + y * 256);
        else                    { v.x = PAD; v.y = PAD; }
#pragma unroll
        for (int i = 0; i < 8; ++i) {
            const int j = u - W - i;
            if (j >= -W && j <= W) {
                const float se = (float)(j * j) * SESC;
                const float cx = fmaf(c, se, v.x);
                const float cy = fmaf(c, se, v.y);
                if (ISMAX) { acc[i].x = fmaxf(acc[i].x, cx); acc[i].y = fmaxf(acc[i].y, cy); }
                else       { acc[i].x = fminf(acc[i].x, cx); acc[i].y = fminf(acc[i].y, cy); }
            }
        }
    }

    float* dp = dst + (size_t)plane * dstPlaneStride + y0 * 256 + x;
#pragma unroll
    for (int i = 0; i < 8; i++) *(float2*)(dp + i * 256) = acc[i];
}

// ---------------------------------------------------------------------------
// Launch: per scale k (W = 4<<k? no: W in {4,8,16,32}, TL = 2k+2):
//   H-dilate(in->A), V-dilate(A->B), H-erode(B->A), V-erode(A->out_k)
// ---------------------------------------------------------------------------
extern "C" void kernel_launch(void* const* d_in, const int* in_sizes, int n_in,
                              void* d_out, int out_size)
{
    (void)in_sizes; (void)n_in; (void)out_size;
    const float* in   = (const float*)d_in[0];
    const float* coef = (const float*)d_in[1];
    float* out = (float*)d_out;

    float *A = nullptr, *B = nullptr;
    cudaGetSymbolAddress((void**)&A, g_bufA);
    cudaGetSymbolAddress((void**)&B, g_bufB);

    dim3 gh(32, NPLANES);   // 32 row-groups x 32 planes
    dim3 gv(16, NPLANES);   // 16 y-groups  x 32 planes

    // scale 0: t=1,  W=4,  TL=2
    hpass<4, 2, true ><<<gh, 256>>>(in, A, coef);
    vpass<4, 2, true ><<<gv, 256>>>(A, B, coef, HW);
    hpass<4, 2, false><<<gh, 256>>>(B, A, coef);
    vpass<4, 2, false><<<gv, 256>>>(A, out + 0 * HW, coef, 4 * HW);

    // scale 1: t=4,  W=8,  TL=4
    hpass<8, 4, true ><<<gh, 256>>>(in, A, coef);
    vpass<8, 4, true ><<<gv, 256>>>(A, B, coef, HW);
    hpass<8, 4, false><<<gh, 256>>>(B, A, coef);
    vpass<8, 4, false><<<gv, 256>>>(A, out + 1 * HW, coef, 4 * HW);

    // scale 2: t=16, W=16, TL=6
    hpass<16, 6, true ><<<gh, 256>>>(in, A, coef);
    vpass<16, 6, true ><<<gv, 256>>>(A, B, coef, HW);
    hpass<16, 6, false><<<gh, 256>>>(B, A, coef);
    vpass<16, 6, false><<<gv, 256>>>(A, out + 2 * HW, coef, 4 * HW);

    // scale 3: t=64, W=32, TL=8
    hpass<32, 8, true ><<<gh, 256>>>(in, A, coef);
    vpass<32, 8, true ><<<gv, 256>>>(A, B, coef, HW);
    hpass<32, 8, false><<<gh, 256>>>(B, A, coef);
    vpass<32, 8, false><<<gv, 256>>>(A, out + 3 * HW, coef, 4 * HW);
}

// round 6
// speedup vs baseline: 1.2614x; 1.2614x over previous
#include <cuda_runtime.h>

#define NPLANES 32
#define HW 65536
#define SCALESZ (NPLANES * HW)   // one scale's full image set (8 MB)

// Per-scale ping-pong scratch: 4 scales x 32 planes x 256x256  (32 MB each)
static __device__ float g_bufA[4 * SCALESZ];
static __device__ float g_bufB[4 * SCALESZ];

// ---------------------------------------------------------------------------
// Horizontal body: weighted sliding max/min along x.
//   out[p] = max_j in[p+j] - c*se(j)  (ISMAX) or min_j in[p+j] + c*se(j)
//   se(j) = j^2 * 2^-TL (exact dyadic). Shared-mem row stride fixed at 320
//   so all W instantiations share one static allocation.
// Block: 256 threads = 8 rows x 32 lanes; each thread -> 8 consecutive x.
// ---------------------------------------------------------------------------
template <int W, int TL, bool ISMAX>
__device__ __forceinline__ void hbody(float* __restrict__ s,           // [8*320]
                                      const float* __restrict__ sp,    // src plane+rowbase
                                      float* __restrict__ dp_base,     // dst plane+rowbase
                                      float c, int t)
{
    constexpr float SESC = 1.0f / (float)(1 << TL);
    constexpr int RW = 256 + 2 * W;
    const float PAD = ISMAX ? -10000.0f : 10000.0f;

    // Stage 8 padded rows into smem (stride 320)
    for (int idx = t; idx < 8 * RW; idx += 256) {
        int rr = idx / RW;
        int pp = idx - rr * RW;
        int xx = pp - W;
        s[rr * 320 + pp] = ((unsigned)xx < 256u) ? sp[rr * 256 + xx] : PAD;
    }
    __syncthreads();

    const int r  = t >> 5;
    const int x0 = (t & 31) * 8;
    const float* srow = s + r * 320 + x0;

    float acc[8];
#pragma unroll
    for (int i = 0; i < 8; i++) acc[i] = ISMAX ? -3.0e38f : 3.0e38f;

    // Source-centric sweep: each smem value read once, feeds up to 8 outputs.
#pragma unroll
    for (int u = 0; u < 2 * W + 8; ++u) {
        const float v = srow[u];
#pragma unroll
        for (int i = 0; i < 8; ++i) {
            const int j = u - W - i;
            if (j >= -W && j <= W) {
                const float se = (float)(j * j) * SESC;   // compile-time const
                const float cand = fmaf(c, se, v);
                acc[i] = ISMAX ? fmaxf(acc[i], cand) : fminf(acc[i], cand);
            }
        }
    }

    float* dp = dp_base + r * 256 + x0;
#pragma unroll
    for (int i = 0; i < 8; i++) dp[i] = acc[i];
}

// All four scales in one launch: blockIdx.z selects scale.
// srcScaleStride = 0 when reading the shared input image, SCALESZ for scratch.
template <bool ISMAX>
__global__ __launch_bounds__(256) void hpass_all(const float* __restrict__ srcBase,
                                                 float* __restrict__ dstBase,
                                                 const float* __restrict__ coefp,
                                                 int srcScaleStride)
{
    __shared__ float s[8 * 320];
    const int scale = blockIdx.z;
    const int plane = blockIdx.y;
    const int rowbase = blockIdx.x * 8;
    const float c = ISMAX ? -__ldg(coefp) : __ldg(coefp);
    const int t = threadIdx.x;

    const float* sp = srcBase + (size_t)scale * srcScaleStride + plane * HW + rowbase * 256;
    float* dp = dstBase + (size_t)scale * SCALESZ + plane * HW + rowbase * 256;

    if      (scale == 0) hbody< 4, 2, ISMAX>(s, sp, dp, c, t);
    else if (scale == 1) hbody< 8, 4, ISMAX>(s, sp, dp, c, t);
    else if (scale == 2) hbody<16, 6, ISMAX>(s, sp, dp, c, t);
    else                 hbody<32, 8, ISMAX>(s, sp, dp, c, t);
}

// ---------------------------------------------------------------------------
// Vertical body: weighted sliding max/min along y, float2-vectorized in x.
// Block: 256 threads = 2 y-subgroups x 128 x-pairs; thread -> 8 rows x 2 cols.
// ---------------------------------------------------------------------------
template <int W, int TL, bool ISMAX>
__device__ __forceinline__ void vbody(const float* __restrict__ sp,  // src plane + x
                                      float* __restrict__ dp,       // dst (already offset)
                                      float c, int y0)
{
    constexpr float SESC = 1.0f / (float)(1 << TL);
    const float PAD = ISMAX ? -10000.0f : 10000.0f;

    float2 acc[8];
    const float INITV = ISMAX ? -3.0e38f : 3.0e38f;
#pragma unroll
    for (int i = 0; i < 8; i++) { acc[i].x = INITV; acc[i].y = INITV; }

#pragma unroll
    for (int u = 0; u < 2 * W + 8; ++u) {
        const int y = y0 - W + u;
        float2 v;
        if ((unsigned)y < 256u) v = *(const float2*)(sp + y * 256);
        else                    { v.x = PAD; v.y = PAD; }
#pragma unroll
        for (int i = 0; i < 8; ++i) {
            const int j = u - W - i;
            if (j >= -W && j <= W) {
                const float se = (float)(j * j) * SESC;
                const float cx = fmaf(c, se, v.x);
                const float cy = fmaf(c, se, v.y);
                if (ISMAX) { acc[i].x = fmaxf(acc[i].x, cx); acc[i].y = fmaxf(acc[i].y, cy); }
                else       { acc[i].x = fminf(acc[i].x, cx); acc[i].y = fminf(acc[i].y, cy); }
            }
        }
    }

#pragma unroll
    for (int i = 0; i < 8; i++) *(float2*)(dp + i * 256) = acc[i];
}

// All four scales in one launch. dst addressing is parameterized so the final
// erosion can write straight into the stacked [B,C,4,H,W] output:
//   dst = dstBase + scale*dstScaleStride + plane*dstPlaneStride + y0*256 + x
template <bool ISMAX>
__global__ __launch_bounds__(256) void vpass_all(const float* __restrict__ srcBase,
                                                 float* __restrict__ dstBase,
                                                 const float* __restrict__ coefp,
                                                 int dstPlaneStride, int dstScaleStride)
{
    const int scale = blockIdx.z;
    const int plane = blockIdx.y;
    const int t = threadIdx.x;
    const int x  = (t & 127) * 2;
    const int y0 = blockIdx.x * 16 + (t >> 7) * 8;
    const float c = ISMAX ? -__ldg(coefp) : __ldg(coefp);

    const float* sp = srcBase + (size_t)scale * SCALESZ + plane * HW + x;
    float* dp = dstBase + (size_t)scale * dstScaleStride
                        + (size_t)plane * dstPlaneStride + y0 * 256 + x;

    if      (scale == 0) vbody< 4, 2, ISMAX>(sp, dp, c, y0);
    else if (scale == 1) vbody< 8, 4, ISMAX>(sp, dp, c, y0);
    else if (scale == 2) vbody<16, 6, ISMAX>(sp, dp, c, y0);
    else                 vbody<32, 8, ISMAX>(sp, dp, c, y0);
}

// ---------------------------------------------------------------------------
// 4 launches total: H-dilate -> V-dilate -> H-erode -> V-erode,
// each covering all 4 scales concurrently (blockIdx.z = scale).
// ---------------------------------------------------------------------------
extern "C" void kernel_launch(void* const* d_in, const int* in_sizes, int n_in,
                              void* d_out, int out_size)
{
    (void)in_sizes; (void)n_in; (void)out_size;
    const float* in   = (const float*)d_in[0];
    const float* coef = (const float*)d_in[1];
    float* out = (float*)d_out;

    float *A = nullptr, *B = nullptr;
    cudaGetSymbolAddress((void**)&A, g_bufA);
    cudaGetSymbolAddress((void**)&B, g_bufB);

    dim3 gh(32, NPLANES, 4);   // 32 row-groups x 32 planes x 4 scales
    dim3 gv(16, NPLANES, 4);   // 16 y-groups  x 32 planes x 4 scales

    hpass_all<true ><<<gh, 256>>>(in, A, coef, /*srcScaleStride=*/0);
    vpass_all<true ><<<gv, 256>>>(A, B, coef, /*dstPlaneStride=*/HW, /*dstScaleStride=*/SCALESZ);
    hpass_all<false><<<gh, 256>>>(B, A, coef, /*srcScaleStride=*/SCALESZ);
    vpass_all<false><<<gv, 256>>>(A, out, coef, /*dstPlaneStride=*/4 * HW, /*dstScaleStride=*/HW);
}

// round 8
// speedup vs baseline: 1.6203x; 1.2845x over previous
#include <cuda_runtime.h>

#define NPLANES 32
#define HW 65536
#define SCALESZ (NPLANES * HW)
#define PR 32                         // vertical pad rows (>= max W)
#define PPL ((256 + 2 * PR) * 256)    // padded plane size in floats (81920)
#define SROW 368                      // skewed smem row stride (floats)

// Scratch:
//  A: padded, written by H-dilate (pads = -1e4), read by V-dilate
//  B: plain,  written by V-dilate, read by H-erode
//  C: padded, written by H-erode (pads = +1e4), read by V-erode
static __device__ float g_bufA[4 * NPLANES * PPL];
static __device__ float g_bufB[4 * SCALESZ];
static __device__ float g_bufC[4 * NPLANES * PPL];

// ---------------------------------------------------------------------------
// Horizontal body (pairwise taps, skewed smem).
//   out[p] = opt_j in[p+j] + c2*se(j),  se(j)=j^2*2^-TL,  c2 = -+coef
// Thread: 8 consecutive x outputs. smem index skew ind(p)=p+(p>>3) makes
// lane-stride-8 accesses conflict-free (effective stride 9, gcd(9,32)=1).
// ---------------------------------------------------------------------------
template <int W, int TL, bool ISMAX>
__device__ __forceinline__ void hbody(float* __restrict__ s,
                                      const float* __restrict__ sp,
                                      float* __restrict__ dp,
                                      float c2, int t)
{
    constexpr float SESC = 1.0f / (float)(1 << TL);
    constexpr int RW = 256 + 2 * W;
    constexpr int J = (W < 8) ? W : 8;
    const float PAD = ISMAX ? -10000.0f : 10000.0f;

    // Stage 8 padded rows into skewed smem
    for (int idx = t; idx < 8 * RW; idx += 256) {
        int rr = idx / RW;
        int pp = idx - rr * RW;
        int xx = pp - W;
        s[rr * SROW + pp + (pp >> 3)] = ((unsigned)xx < 256u) ? sp[rr * 256 + xx] : PAD;
    }
    __syncthreads();

    const int r  = t >> 5;
    const int x0 = (t & 31) * 8;                 // multiple of 8
    const float* srow = s + r * SROW + x0 + (x0 >> 3);

    float acc[8];
#pragma unroll
    for (int i = 0; i < 8; i++)                  // center tap (weight 0)
        acc[i] = srow[(W + i) + ((W + i) >> 3)];

#pragma unroll
    for (int j0 = 1; j0 <= W; j0 += J) {
        const int klo  = W - j0 - (J - 1);       // lo window base (multiple of 8)
        const int kloA = klo & ~7;
        const int dlo  = klo - kloA;
        const int khi  = W + j0;                 // hi window base
        const int khiA = khi & ~7;
        const int dhi  = khi - khiA;

        float lov[J + 14], hiv[J + 14];
#pragma unroll
        for (int m = 0; m < dlo + J + 7; m++)
            lov[m] = srow[kloA + (kloA >> 3) + m + (m >> 3)];
#pragma unroll
        for (int m = 0; m < dhi + J + 7; m++)
            hiv[m] = srow[khiA + (khiA >> 3) + m + (m >> 3)];

#pragma unroll
        for (int jj = 0; jj < J; jj++) {
            const int j = j0 + jj;
            const float jw = (float)(j * j) * SESC;   // exact compile-time const
#pragma unroll
            for (int i = 0; i < 8; i++) {
                const float a = lov[dlo + (J - 1) + i - jj];   // in[p - j]
                const float b = hiv[dhi + i + jj];             // in[p + j]
                const float pm = ISMAX ? fmaxf(a, b) : fminf(a, b);
                const float cand = fmaf(c2, jw, pm);
                acc[i] = ISMAX ? fmaxf(acc[i], cand) : fminf(acc[i], cand);
            }
        }
    }

    float* d = dp + r * 256 + x0;
    *(float4*)(d + 0) = make_float4(acc[0], acc[1], acc[2], acc[3]);
    *(float4*)(d + 4) = make_float4(acc[4], acc[5], acc[6], acc[7]);
}

// H pass, all 4 scales per launch. Writes into a vertically padded buffer and
// uses 8 extra blocks per plane (g>=32) to fill the pad rows with +-1e4.
template <bool ISMAX>
__global__ __launch_bounds__(256, 2) void hpass_all(const float* __restrict__ src,
                                                    float* __restrict__ dstPad,
                                                    const float* __restrict__ coefp,
                                                    int srcScaleStride)
{
    __shared__ float s[8 * SROW];
    const int scale = blockIdx.z;
    const int plane = blockIdx.y;
    const int g = blockIdx.x;          // 0..39 : 32 row-groups + 8 pad-fill groups
    const int t = threadIdx.x;
    float* dplane = dstPad + (size_t)(scale * NPLANES + plane) * PPL;

    if (g >= 32) {                     // fill 8 pad rows with PAD
        const float PAD = ISMAX ? -10000.0f : 10000.0f;
        const int pr = (g - 32) * 8;   // 0..63 within the 64 pad rows
        const int prow = (pr < PR) ? pr : (pr + 256);  // padded-row index
        const float4 pv = make_float4(PAD, PAD, PAD, PAD);
        for (int idx = t; idx < 8 * 64; idx += 256) {
            int rr = idx >> 6, cc = idx & 63;
            *(float4*)(dplane + (prow + rr) * 256 + cc * 4) = pv;
        }
        return;
    }

    const float c = __ldg(coefp);
    const float c2 = ISMAX ? -c : c;
    const int rowbase = g * 8;
    const float* sp = src + (size_t)scale * srcScaleStride + plane * HW + rowbase * 256;
    float* dp = dplane + (PR + rowbase) * 256;

    if      (scale == 0) hbody< 4, 2, ISMAX>(s, sp, dp, c2, t);
    else if (scale == 1) hbody< 8, 4, ISMAX>(s, sp, dp, c2, t);
    else if (scale == 2) hbody<16, 6, ISMAX>(s, sp, dp, c2, t);
    else                 hbody<32, 8, ISMAX>(s, sp, dp, c2, t);
}

// ---------------------------------------------------------------------------
// Vertical body (pairwise taps, padded global source -> no bounds checks).
// Thread: 8 consecutive y outputs x 2 x-columns (float2).
// ---------------------------------------------------------------------------
template <int W, int TL, bool ISMAX>
__device__ __forceinline__ void vbody(const float* __restrict__ sp,
                                      float* __restrict__ dp,
                                      float c2, int y0)
{
    constexpr float SESC = 1.0f / (float)(1 << TL);
    constexpr int J = (W < 8) ? W : 8;

    float2 acc[8];
#pragma unroll
    for (int i = 0; i < 8; i++)                  // center tap
        acc[i] = *(const float2*)(sp + (y0 + i) * 256);

#pragma unroll
    for (int j0 = 1; j0 <= W; j0 += J) {
        float2 lov[J + 7], hiv[J + 7];
#pragma unroll
        for (int m = 0; m < J + 7; m++) {
            lov[m] = *(const float2*)(sp + (y0 - j0 - (J - 1) + m) * 256);
            hiv[m] = *(const float2*)(sp + (y0 + j0 + m) * 256);
        }
#pragma unroll
        for (int jj = 0; jj < J; jj++) {
            const int j = j0 + jj;
            const float jw = (float)(j * j) * SESC;
#pragma unroll
            for (int i = 0; i < 8; i++) {
                const float2 a = lov[(J - 1) + i - jj];   // row p - j
                const float2 b = hiv[i + jj];             // row p + j
                const float px = ISMAX ? fmaxf(a.x, b.x) : fminf(a.x, b.x);
                const float py = ISMAX ? fmaxf(a.y, b.y) : fminf(a.y, b.y);
                const float cx = fmaf(c2, jw, px);
                const float cy = fmaf(c2, jw, py);
                acc[i].x = ISMAX ? fmaxf(acc[i].x, cx) : fminf(acc[i].x, cx);
                acc[i].y = ISMAX ? fmaxf(acc[i].y, cy) : fminf(acc[i].y, cy);
            }
        }
    }

#pragma unroll
    for (int i = 0; i < 8; i++)
        *(float2*)(dp + i * 256) = acc[i];
}

template <bool ISMAX>
__global__ __launch_bounds__(256, 2) void vpass_all(const float* __restrict__ srcPad,
                                                    float* __restrict__ dst,
                                                    const float* __restrict__ coefp,
                                                    int dstPlaneStride, int dstScaleStride)
{
    const int scale = blockIdx.z;
    const int plane = blockIdx.y;
    const int t = threadIdx.x;
    const int x  = (t & 127) * 2;
    const int y0 = blockIdx.x * 16 + (t >> 7) * 8;
    const float c = __ldg(coefp);
    const float c2 = ISMAX ? -c : c;

    const float* sp = srcPad + (size_t)(scale * NPLANES + plane) * PPL + PR * 256 + x;
    float* dp = dst + (size_t)scale * dstScaleStride
                    + (size_t)plane * dstPlaneStride + y0 * 256 + x;

    if      (scale == 0) vbody< 4, 2, ISMAX>(sp, dp, c2, y0);
    else if (scale == 1) vbody< 8, 4, ISMAX>(sp, dp, c2, y0);
    else if (scale == 2) vbody<16, 6, ISMAX>(sp, dp, c2, y0);
    else                 vbody<32, 8, ISMAX>(sp, dp, c2, y0);
}

// ---------------------------------------------------------------------------
// 4 launches: H-dilate(in->A,+pads) -> V-dilate(A->B) -> H-erode(B->C,+pads)
//             -> V-erode(C->out)
// ---------------------------------------------------------------------------
extern "C" void kernel_launch(void* const* d_in, const int* in_sizes, int n_in,
                              void* d_out, int out_size)
{
    (void)in_sizes; (void)n_in; (void)out_size;
    const float* in   = (const float*)d_in[0];
    const float* coef = (const float*)d_in[1];
    float* out = (float*)d_out;

    float *A = nullptr, *B = nullptr, *C = nullptr;
    cudaGetSymbolAddress((void**)&A, g_bufA);
    cudaGetSymbolAddress((void**)&B, g_bufB);
    cudaGetSymbolAddress((void**)&C, g_bufC);

    dim3 gh(40, NPLANES, 4);   // 32 row-groups + 8 pad-fill groups
    dim3 gv(16, NPLANES, 4);

    hpass_all<true ><<<gh, 256>>>(in, A, coef, /*srcScaleStride=*/0);
    vpass_all<true ><<<gv, 256>>>(A, B, coef, /*dstPlaneStride=*/HW, /*dstScaleStride=*/SCALESZ);
    hpass_all<false><<<gh, 256>>>(B, C, coef, /*srcScaleStride=*/SCALESZ);
    vpass_all<false><<<gv, 256>>>(C, out, coef, /*dstPlaneStride=*/4 * HW, /*dstScaleStride=*/HW);
}

// round 12
// speedup vs baseline: 1.6503x; 1.0185x over previous
#include <cuda_runtime.h>

#define NPLANES 32
#define HW 65536
#define SCALESZ (NPLANES * HW)
#define PR 32                         // vertical pad rows (>= max W)
#define PPL ((256 + 2 * PR) * 256)    // padded plane size in floats (81920)
#define SROW 368                      // skewed smem row stride (floats)

// Scratch:
//  A: padded, written by H-dilate (pads = -1e4), read by V-dilate
//  B: plain,  written by V-dilate, read by H-erode
//  C: padded, written by H-erode (pads = +1e4), read by V-erode
static __device__ float g_bufA[4 * NPLANES * PPL];
static __device__ float g_bufB[4 * SCALESZ];
static __device__ float g_bufC[4 * NPLANES * PPL];

// ---------------------------------------------------------------------------
// Horizontal body (pairwise symmetric taps, skewed smem).
//   out[p] = opt_j in[p+j] + c2*se(j),  se(j)=j^2*2^-TL,  c2 = -+coef
//   pairwise: opt over j>0 of (opt(in[p-j], in[p+j]) + c2*se(j))  -- exact,
//   since max/min are order-preserving and c2*se is an exact dyadic product.
// Thread: 8 consecutive x outputs. smem index skew ind(p)=p+(p>>3) makes
// lane-stride-8 accesses conflict-free (effective stride 9, gcd(9,32)=1).
// ---------------------------------------------------------------------------
template <int W, int TL, bool ISMAX>
__device__ __forceinline__ void hbody(float* __restrict__ s,
                                      const float* __restrict__ sp,
                                      float* __restrict__ dp,
                                      float c2, int t)
{
    constexpr float SESC = 1.0f / (float)(1 << TL);
    constexpr int RW = 256 + 2 * W;
    constexpr int J = (W < 8) ? W : 8;
    const float PAD = ISMAX ? -10000.0f : 10000.0f;

    // Stage 8 padded rows into skewed smem
    for (int idx = t; idx < 8 * RW; idx += 256) {
        int rr = idx / RW;
        int pp = idx - rr * RW;
        int xx = pp - W;
        s[rr * SROW + pp + (pp >> 3)] = ((unsigned)xx < 256u) ? sp[rr * 256 + xx] : PAD;
    }
    __syncthreads();

    const int r  = t >> 5;
    const int x0 = (t & 31) * 8;                 // multiple of 8
    const float* srow = s + r * SROW + x0 + (x0 >> 3);

    float acc[8];
#pragma unroll
    for (int i = 0; i < 8; i++)                  // center tap (weight 0)
        acc[i] = srow[(W + i) + ((W + i) >> 3)];

#pragma unroll
    for (int j0 = 1; j0 <= W; j0 += J) {
        const int klo  = W - j0 - (J - 1);       // lo window base
        const int kloA = klo & ~7;               // align to 8 (skew const-folds)
        const int dlo  = klo - kloA;
        const int khi  = W + j0;                 // hi window base
        const int khiA = khi & ~7;
        const int dhi  = khi - khiA;

        float lov[J + 14], hiv[J + 14];
#pragma unroll
        for (int m = 0; m < dlo + J + 7; m++)
            lov[m] = srow[kloA + (kloA >> 3) + m + (m >> 3)];
#pragma unroll
        for (int m = 0; m < dhi + J + 7; m++)
            hiv[m] = srow[khiA + (khiA >> 3) + m + (m >> 3)];

#pragma unroll
        for (int jj = 0; jj < J; jj++) {
            const int j = j0 + jj;
            const float jw = (float)(j * j) * SESC;   // exact compile-time const
#pragma unroll
            for (int i = 0; i < 8; i++) {
                const float a = lov[dlo + (J - 1) + i - jj];   // in[p - j]
                const float b = hiv[dhi + i + jj];             // in[p + j]
                const float pm = ISMAX ? fmaxf(a, b) : fminf(a, b);
                const float cand = fmaf(c2, jw, pm);
                acc[i] = ISMAX ? fmaxf(acc[i], cand) : fminf(acc[i], cand);
            }
        }
    }

    float* d = dp + r * 256 + x0;
    *(float4*)(d + 0) = make_float4(acc[0], acc[1], acc[2], acc[3]);
    *(float4*)(d + 4) = make_float4(acc[4], acc[5], acc[6], acc[7]);
}

// H pass, all 4 scales per launch. Writes into a vertically padded buffer and
// uses 8 extra blocks per plane (g>=32) to fill the pad rows with +-1e4.
template <bool ISMAX>
__global__ __launch_bounds__(256, 3) void hpass_all(const float* __restrict__ src,
                                                    float* __restrict__ dstPad,
                                                    const float* __restrict__ coefp,
                                                    int srcScaleStride)
{
    __shared__ float s[8 * SROW];
    const int scale = blockIdx.z;
    const int plane = blockIdx.y;
    const int g = blockIdx.x;          // 0..39 : 32 row-groups + 8 pad-fill groups
    const int t = threadIdx.x;
    float* dplane = dstPad + (size_t)(scale * NPLANES + plane) * PPL;

    if (g >= 32) {                     // fill 8 pad rows with PAD
        const float PAD = ISMAX ? -10000.0f : 10000.0f;
        const int pr = (g - 32) * 8;   // 0..63 within the 64 pad rows
        const int prow = (pr < PR) ? pr : (pr + 256);  // padded-row index
        const float4 pv = make_float4(PAD, PAD, PAD, PAD);
        for (int idx = t; idx < 8 * 64; idx += 256) {
            int rr = idx >> 6, cc = idx & 63;
            *(float4*)(dplane + (prow + rr) * 256 + cc * 4) = pv;
        }
        return;
    }

    const float c = __ldg(coefp);
    const float c2 = ISMAX ? -c : c;
    const int rowbase = g * 8;
    const float* sp = src + (size_t)scale * srcScaleStride + plane * HW + rowbase * 256;
    float* dp = dplane + (PR + rowbase) * 256;

    if      (scale == 0) hbody< 4, 2, ISMAX>(s, sp, dp, c2, t);
    else if (scale == 1) hbody< 8, 4, ISMAX>(s, sp, dp, c2, t);
    else if (scale == 2) hbody<16, 6, ISMAX>(s, sp, dp, c2, t);
    else                 hbody<32, 8, ISMAX>(s, sp, dp, c2, t);
}

// ---------------------------------------------------------------------------
// Vertical body (pairwise taps, padded global source -> no bounds checks).
// Thread: 8 consecutive y outputs x 2 x-columns (float2).
// J=4 chunking keeps register windows small (2 x 11 float2) so 3 CTAs/SM fit.
// ---------------------------------------------------------------------------
template <int W, int TL, bool ISMAX>
__device__ __forceinline__ void vbody(const float* __restrict__ sp,
                                      float* __restrict__ dp,
                                      float c2, int y0)
{
    constexpr float SESC = 1.0f / (float)(1 << TL);
    constexpr int J = (W < 4) ? W : 4;

    float2 acc[8];
#pragma unroll
    for (int i = 0; i < 8; i++)                  // center tap
        acc[i] = *(const float2*)(sp + (y0 + i) * 256);

#pragma unroll
    for (int j0 = 1; j0 <= W; j0 += J) {
        float2 lov[J + 7], hiv[J + 7];
#pragma unroll
        for (int m = 0; m < J + 7; m++) {
            lov[m] = *(const float2*)(sp + (y0 - j0 - (J - 1) + m) * 256);
            hiv[m] = *(const float2*)(sp + (y0 + j0 + m) * 256);
        }
#pragma unroll
        for (int jj = 0; jj < J; jj++) {
            const int j = j0 + jj;
            const float jw = (float)(j * j) * SESC;
#pragma unroll
            for (int i = 0; i < 8; i++) {
                const float2 a = lov[(J - 1) + i - jj];   // row p - j
                const float2 b = hiv[i + jj];             // row p + j
                const float px = ISMAX ? fmaxf(a.x, b.x) : fminf(a.x, b.x);
                const float py = ISMAX ? fmaxf(a.y, b.y) : fminf(a.y, b.y);
                const float cx = fmaf(c2, jw, px);
                const float cy = fmaf(c2, jw, py);
                acc[i].x = ISMAX ? fmaxf(acc[i].x, cx) : fminf(acc[i].x, cx);
                acc[i].y = ISMAX ? fmaxf(acc[i].y, cy) : fminf(acc[i].y, cy);
            }
        }
    }

#pragma unroll
    for (int i = 0; i < 8; i++)
        *(float2*)(dp + i * 256) = acc[i];
}

template <bool ISMAX>
__global__ __launch_bounds__(256, 3) void vpass_all(const float* __restrict__ srcPad,
                                                    float* __restrict__ dst,
                                                    const float* __restrict__ coefp,
                                                    int dstPlaneStride, int dstScaleStride)
{
    const int scale = blockIdx.z;
    const int plane = blockIdx.y;
    const int t = threadIdx.x;
    const int x  = (t & 127) * 2;
    const int y0 = blockIdx.x * 16 + (t >> 7) * 8;
    const float c = __ldg(coefp);
    const float c2 = ISMAX ? -c : c;

    const float* sp = srcPad + (size_t)(scale * NPLANES + plane) * PPL + PR * 256 + x;
    float* dp = dst + (size_t)scale * dstScaleStride
                    + (size_t)plane * dstPlaneStride + y0 * 256 + x;

    if      (scale == 0) vbody< 4, 2, ISMAX>(sp, dp, c2, y0);
    else if (scale == 1) vbody< 8, 4, ISMAX>(sp, dp, c2, y0);
    else if (scale == 2) vbody<16, 6, ISMAX>(sp, dp, c2, y0);
    else                 vbody<32, 8, ISMAX>(sp, dp, c2, y0);
}

// ---------------------------------------------------------------------------
// 4 launches: H-dilate(in->A,+pads) -> V-dilate(A->B) -> H-erode(B->C,+pads)
//             -> V-erode(C->out)
// ---------------------------------------------------------------------------
extern "C" void kernel_launch(void* const* d_in, const int* in_sizes, int n_in,
                              void* d_out, int out_size)
{
    (void)in_sizes; (void)n_in; (void)out_size;
    const float* in   = (const float*)d_in[0];
    const float* coef = (const float*)d_in[1];
    float* out = (float*)d_out;

    float *A = nullptr, *B = nullptr, *C = nullptr;
    cudaGetSymbolAddress((void**)&A, g_bufA);
    cudaGetSymbolAddress((void**)&B, g_bufB);
    cudaGetSymbolAddress((void**)&C, g_bufC);

    dim3 gh(40, NPLANES, 4);   // 32 row-groups + 8 pad-fill groups
    dim3 gv(16, NPLANES, 4);

    hpass_all<true ><<<gh, 256>>>(in, A, coef, /*srcScaleStride=*/0);
    vpass_all<true ><<<gv, 256>>>(A, B, coef, /*dstPlaneStride=*/HW, /*dstScaleStride=*/SCALESZ);
    hpass_all<false><<<gh, 256>>>(B, C, coef, /*srcScaleStride=*/SCALESZ);
    vpass_all<false><<<gv, 256>>>(C, out, coef, /*dstPlaneStride=*/4 * HW, /*dstScaleStride=*/HW);
}

// round 15
// speedup vs baseline: 1.6889x; 1.0233x over previous
#include <cuda_runtime.h>

#define NPLANES 32
#define HW 65536
#define PR 32                         // vertical pad rows (>= max W)
#define PPL ((256 + 2 * PR) * 256)    // padded plane size in floats
#define SROW 368                      // skewed smem row stride (floats)
#define P32 32                        // uniform horizontal pad in staged tiles

// A: y-padded H-dilate result (pads -1e4).  C: y-padded H-erode result (pads +1e4).
static __device__ float g_bufA[4 * NPLANES * PPL];
static __device__ float g_bufC[4 * NPLANES * PPL];

// ---------------------------------------------------------------------------
// hmath: horizontal weighted opt over a staged smem row (uniform pad P32=32,
// skew ind(p)=p+(p>>3), row already padded/PAD-filled). 8 outputs at x0..x0+7.
//   out[p] = opt_j tile[p+j] + c2*se(j),  se(j)=j^2*2^-TL exact dyadic.
// Pairing max(a,b)+w == max(a+w,b+w) exactly (order-preserving + exact w).
// ---------------------------------------------------------------------------
template <int W, int TL, bool ISMAX>
__device__ __forceinline__ void hmath(const float* __restrict__ srow0, // s + row*SROW
                                      float* __restrict__ dout,       // global, 8 floats
                                      float c2, int x0)
{
    constexpr float SESC = 1.0f / (float)(1 << TL);
    constexpr int J = (W < 8) ? W : 8;
    const float* srow = srow0 + x0 + (x0 >> 3);   // x0 multiple of 8

    float acc[8];
#pragma unroll
    for (int i = 0; i < 8; i++)                   // center tap (weight 0)
        acc[i] = srow[(P32 + i) + ((P32 + i) >> 3)];

#pragma unroll
    for (int j0 = 1; j0 <= W; j0 += J) {
        const int klo  = P32 - j0 - (J - 1);      // >= 0 for all scales
        const int kloA = klo & ~7;
        const int dlo  = klo - kloA;
        const int khi  = P32 + j0;
        const int khiA = khi & ~7;
        const int dhi  = khi - khiA;

        float lov[J + 14], hiv[J + 14];
#pragma unroll
        for (int m = 0; m < dlo + J + 7; m++)
            lov[m] = srow[kloA + (kloA >> 3) + m + (m >> 3)];
#pragma unroll
        for (int m = 0; m < dhi + J + 7; m++)
            hiv[m] = srow[khiA + (khiA >> 3) + m + (m >> 3)];

#pragma unroll
        for (int jj = 0; jj < J; jj++) {
            const int j = j0 + jj;
            const float jw = (float)(j * j) * SESC;
#pragma unroll
            for (int i = 0; i < 8; i++) {
                const float a = lov[dlo + (J - 1) + i - jj];   // tile[p - j]
                const float b = hiv[dhi + i + jj];             // tile[p + j]
                const float pm = ISMAX ? fmaxf(a, b) : fminf(a, b);
                const float cand = fmaf(c2, jw, pm);
                acc[i] = ISMAX ? fmaxf(acc[i], cand) : fminf(acc[i], cand);
            }
        }
    }

    *(float4*)(dout + 0) = make_float4(acc[0], acc[1], acc[2], acc[3]);
    *(float4*)(dout + 4) = make_float4(acc[4], acc[5], acc[6], acc[7]);
}

// ---------------------------------------------------------------------------
// K1: H-dilate, ALL 4 scales from one shared staged tile (8 rows, pad 32).
// g>=32 blocks fill A's vertical pad rows (-1e4) for all scales.
// ---------------------------------------------------------------------------
__global__ __launch_bounds__(256, 3) void hdil_all(const float* __restrict__ in,
                                                   float* __restrict__ Apad,
                                                   const float* __restrict__ coefp)
{
    __shared__ float s[8 * SROW];
    const int g = blockIdx.x;          // 0..39: 32 row-groups + 8 pad-fill groups
    const int plane = blockIdx.y;
    const int t = threadIdx.x;
    const float PAD = -10000.0f;

    if (g >= 32) {
        const int pr = (g - 32) * 8;                    // 0..63
        const int prow = (pr < PR) ? pr : (pr + 256);   // padded-row index
        const float4 pv = make_float4(PAD, PAD, PAD, PAD);
#pragma unroll
        for (int sc = 0; sc < 4; sc++) {
            float* dpl = Apad + (size_t)(sc * NPLANES + plane) * PPL;
            for (int idx = t; idx < 8 * 64; idx += 256) {
                int rr = idx >> 6, cc = idx & 63;
                *(float4*)(dpl + (prow + rr) * 256 + cc * 4) = pv;
            }
        }
        return;
    }

    const float c2 = -__ldg(coefp);
    const int rowbase = g * 8;
    const float* sp = in + plane * HW + rowbase * 256;

    // Stage 8 rows once, pad 32 each side
    for (int idx = t; idx < 8 * 320; idx += 256) {
        int rr = idx / 320;
        int pp = idx - rr * 320;
        int xx = pp - P32;
        s[rr * SROW + pp + (pp >> 3)] = ((unsigned)xx < 256u) ? sp[rr * 256 + xx] : PAD;
    }
    __syncthreads();

    const int r  = t >> 5;
    const int x0 = (t & 31) * 8;
    const float* srow = s + r * SROW;
    const size_t drow = (size_t)(PR + rowbase + r) * 256 + x0 + (size_t)plane * PPL;

    hmath< 4, 2, true>(srow, Apad + (size_t)(0 * NPLANES) * PPL + drow, c2, x0);
    hmath< 8, 4, true>(srow, Apad + (size_t)(1 * NPLANES) * PPL + drow, c2, x0);
    hmath<16, 6, true>(srow, Apad + (size_t)(2 * NPLANES) * PPL + drow, c2, x0);
    hmath<32, 8, true>(srow, Apad + (size_t)(3 * NPLANES) * PPL + drow, c2, x0);
}

// ---------------------------------------------------------------------------
// K2 body: fused V-dilate (global A -> smem, 16-row strip, full width)
//          then H-erode (smem -> global C).
// ---------------------------------------------------------------------------
template <int W, int TL>
__device__ __forceinline__ void k2body(const float* __restrict__ Apl, // plane + PR rows
                                       float* __restrict__ s,         // [16*SROW]
                                       float* __restrict__ Cpl,       // plane + PR rows
                                       float cdil, float cero,
                                       int t, int ytile)
{
    constexpr float SESC = 1.0f / (float)(1 << TL);
    constexpr int J = (W < 4) ? W : 4;

    // ---- V-dilate: thread = 2 cols x 8 rows ----
    {
        const int x  = (t & 127) * 2;
        const int y0 = ytile + (t >> 7) * 8;
        const float* sp = Apl + x;

        float2 acc[8];
#pragma unroll
        for (int i = 0; i < 8; i++)              // center tap
            acc[i] = *(const float2*)(sp + (y0 + i) * 256);

#pragma unroll
        for (int j0 = 1; j0 <= W; j0 += J) {
            float2 lov[J + 7], hiv[J + 7];
#pragma unroll
            for (int m = 0; m < J + 7; m++) {
                lov[m] = *(const float2*)(sp + (y0 - j0 - (J - 1) + m) * 256);
                hiv[m] = *(const float2*)(sp + (y0 + j0 + m) * 256);
            }
#pragma unroll
            for (int jj = 0; jj < J; jj++) {
                const int j = j0 + jj;
                const float jw = (float)(j * j) * SESC;
#pragma unroll
                for (int i = 0; i < 8; i++) {
                    const float2 a = lov[(J - 1) + i - jj];
                    const float2 b = hiv[i + jj];
                    const float px = fmaxf(a.x, b.x);
                    const float py = fmaxf(a.y, b.y);
                    const float cx = fmaf(cdil, jw, px);
                    const float cy = fmaf(cdil, jw, py);
                    acc[i].x = fmaxf(acc[i].x, cx);
                    acc[i].y = fmaxf(acc[i].y, cy);
                }
            }
        }

        // park in smem at p = 32 + x (p even -> p,p+1 in same skew block)
        const int lr0 = (t >> 7) * 8;
        const int p = P32 + x;
#pragma unroll
        for (int i = 0; i < 8; i++) {
            const int bi = (lr0 + i) * SROW + p + (p >> 3);
            s[bi]     = acc[i].x;
            s[bi + 1] = acc[i].y;
        }
    }

    // x-pad fill for the 16 rows: cols [0,32) and [288,320) get +1e4 (erosion pad)
    for (int idx = t; idx < 16 * 64; idx += 256) {
        int rr = idx >> 6, cc = idx & 63;
        int p = (cc < 32) ? cc : (cc + 256);
        s[rr * SROW + p + (p >> 3)] = 10000.0f;
    }
    __syncthreads();

    // ---- H-erode from smem: thread = 8 cols x 2 rows (r, r+8) ----
    {
        const int r  = t >> 5;
        const int x0 = (t & 31) * 8;
#pragma unroll
        for (int h = 0; h < 2; h++) {
            const int row = h * 8 + r;
            float* dp = Cpl + (size_t)(ytile + row) * 256 + x0;
            hmath<W, TL, false>(s + row * SROW, dp, cero, x0);
        }
    }
}

__global__ __launch_bounds__(256, 3) void vdil_hero_all(const float* __restrict__ Apad,
                                                        float* __restrict__ Cpad,
                                                        const float* __restrict__ coefp)
{
    __shared__ float s[16 * SROW];
    const int scale = blockIdx.z;
    const int plane = blockIdx.y;
    const int gx = blockIdx.x;         // 0..19: 16 strips + 4 pad-fill groups
    const int t = threadIdx.x;
    float* Cpl = Cpad + (size_t)(scale * NPLANES + plane) * PPL;

    if (gx >= 16) {                    // fill C's 64 vertical pad rows with +1e4
        const int pr = (gx - 16) * 16;                 // 0,16,32,48
        const int prow = (pr < PR) ? pr : (pr + 256);
        const float4 pv = make_float4(10000.0f, 10000.0f, 10000.0f, 10000.0f);
        for (int idx = t; idx < 16 * 64; idx += 256) {
            int rr = idx >> 6, cc = idx & 63;
            *(float4*)(Cpl + (prow + rr) * 256 + cc * 4) = pv;
        }
        return;
    }

    const float c = __ldg(coefp);
    const float* Apl = Apad + (size_t)(scale * NPLANES + plane) * PPL + PR * 256;
    float* CplD = Cpl + PR * 256;
    const int ytile = gx * 16;

    if      (scale == 0) k2body< 4, 2>(Apl, s, CplD, -c, c, t, ytile);
    else if (scale == 1) k2body< 8, 4>(Apl, s, CplD, -c, c, t, ytile);
    else if (scale == 2) k2body<16, 6>(Apl, s, CplD, -c, c, t, ytile);
    else                 k2body<32, 8>(Apl, s, CplD, -c, c, t, ytile);
}

// ---------------------------------------------------------------------------
// K3: V-erode (padded C -> stacked output), thread = 2 cols x 8 rows.
// ---------------------------------------------------------------------------
template <int W, int TL>
__device__ __forceinline__ void vero_body(const float* __restrict__ sp,
                                          float* __restrict__ dp,
                                          float c2, int y0)
{
    constexpr float SESC = 1.0f / (float)(1 << TL);
    constexpr int J = (W < 4) ? W : 4;

    float2 acc[8];
#pragma unroll
    for (int i = 0; i < 8; i++)
        acc[i] = *(const float2*)(sp + (y0 + i) * 256);

#pragma unroll
    for (int j0 = 1; j0 <= W; j0 += J) {
        float2 lov[J + 7], hiv[J + 7];
#pragma unroll
        for (int m = 0; m < J + 7; m++) {
            lov[m] = *(const float2*)(sp + (y0 - j0 - (J - 1) + m) * 256);
            hiv[m] = *(const float2*)(sp + (y0 + j0 + m) * 256);
        }
#pragma unroll
        for (int jj = 0; jj < J; jj++) {
            const int j = j0 + jj;
            const float jw = (float)(j * j) * SESC;
#pragma unroll
            for (int i = 0; i < 8; i++) {
                const float2 a = lov[(J - 1) + i - jj];
                const float2 b = hiv[i + jj];
                const float px = fminf(a.x, b.x);
                const float py = fminf(a.y, b.y);
                const float cx = fmaf(c2, jw, px);
                const float cy = fmaf(c2, jw, py);
                acc[i].x = fminf(acc[i].x, cx);
                acc[i].y = fminf(acc[i].y, cy);
            }
        }
    }

#pragma unroll
    for (int i = 0; i < 8; i++)
        *(float2*)(dp + i * 256) = acc[i];
}

__global__ __launch_bounds__(256, 3) void vero_all(const float* __restrict__ Cpad,
                                                   float* __restrict__ dst,
                                                   const float* __restrict__ coefp)
{
    const int scale = blockIdx.z;
    const int plane = blockIdx.y;
    const int t = threadIdx.x;
    const int x  = (t & 127) * 2;
    const int y0 = blockIdx.x * 16 + (t >> 7) * 8;
    const float c2 = __ldg(coefp);

    const float* sp = Cpad + (size_t)(scale * NPLANES + plane) * PPL + PR * 256 + x;
    float* dp = dst + (size_t)scale * HW + (size_t)plane * 4 * HW + y0 * 256 + x;

    if      (scale == 0) vero_body< 4, 2>(sp, dp, c2, y0);
    else if (scale == 1) vero_body< 8, 4>(sp, dp, c2, y0);
    else if (scale == 2) vero_body<16, 6>(sp, dp, c2, y0);
    else                 vero_body<32, 8>(sp, dp, c2, y0);
}

// ---------------------------------------------------------------------------
// 3 launches: H-dil(all scales, in->A) -> fused V-dil+H-ero (A->C) -> V-ero(C->out)
// ---------------------------------------------------------------------------
extern "C" void kernel_launch(void* const* d_in, const int* in_sizes, int n_in,
                              void* d_out, int out_size)
{
    (void)in_sizes; (void)n_in; (void)out_size;
    const float* in   = (const float*)d_in[0];
    const float* coef = (const float*)d_in[1];
    float* out = (float*)d_out;

    float *A = nullptr, *C = nullptr;
    cudaGetSymbolAddress((void**)&A, g_bufA);
    cudaGetSymbolAddress((void**)&C, g_bufC);

    dim3 g1(40, NPLANES);        // 32 row-groups + 8 pad-fill groups (all scales inside)
    dim3 g2(20, NPLANES, 4);     // 16 strips + 4 pad-fill groups
    dim3 g3(16, NPLANES, 4);

    hdil_all     <<<g1, 256>>>(in, A, coef);
    vdil_hero_all<<<g2, 256>>>(A, C, coef);
    vero_all     <<<g3, 256>>>(C, out, coef);
}